// round 13
// baseline (speedup 1.0000x reference)
#include <cuda_runtime.h>
#include <cstdint>

// Problem constants
#define BB   16
#define CIN  8
#define COUT 32
#define HH   64
#define WW   64
#define K2   9
#define NC   8          // spline coefficients per feature
#define NF   9          // features per cin: silu + 8 spline bases
#define TILE 16
#define NTILES 16       // 4x4 tiles of 16x16
#define THREADS 512

#define FR    18                       // halo rows
#define FCR   18                       // real halo cols
#define FCP   20                       // padded col stride (+swizzle slot)
#define FPIX_S (FR * FCP)              // 360 floats per plane (stored)
#define FPIX_R (FR * FCR)              // 324 real pixels
#define SF_FLOATS (NF * FPIX_S)        // 3240
#define WCHUNK   (NF * K2 * COUT)      // 2592 floats per cin

// Row swizzle: +1 for rows whose pair-index is odd -> warp feature LDS
// spreads across all 32 banks (2x2 px blocking makes raw offsets even).
#define SWZ(hr) (((hr) >> 1) & 1)

// Fused weights + tiled, swizzle-baked feature images (kan_prep_kernel).
// g_feat_t[(b*CIN+c)*NTILES + tile][f][FPIX_S] == exact smem image per tile.
__device__ float g_fused[CIN * WCHUNK];
__device__ float g_feat_t[(size_t)BB * CIN * NTILES * SF_FLOATS];   // ~26.5 MB

__device__ __forceinline__ float silu_f(float x) {
    return x / (1.0f + __expf(-x));
}

// Packed f32x2 FMA: one issue slot, two fp32 FMAs, bit-identical rounding.
__device__ __forceinline__ void ffma2(unsigned long long& d,
                                      unsigned long long a,
                                      unsigned long long b) {
    asm("fma.rn.f32x2 %0, %1, %2, %0;" : "+l"(d) : "l"(a), "l"(b));
}

__device__ __forceinline__ unsigned long long pack2(float v) {
    unsigned long long p;
    asm("mov.b64 %0, {%1, %1};" : "=l"(p) : "f"(v));
    return p;
}

__device__ __forceinline__ void unpack2(unsigned long long p, float& lo, float& hi) {
    asm("mov.b64 {%0, %1}, %2;" : "=f"(lo), "=f"(hi) : "l"(p));
}

__device__ __forceinline__ void cp_async16(uint32_t saddr, const void* gptr) {
    asm volatile("cp.async.cg.shared.global [%0], [%1], 16;"
                 :: "r"(saddr), "l"(gptr));
}

// De Boor-Cox recursion, degree 3, uniform knots t[j] = (j-3)*0.4 - 1.0.
// Uniform knots => denominators are exactly k*h; divisions replaced by
// compile-time reciprocal multiplies (deviation ~1e-7, tolerance 1e-3).
__device__ __forceinline__ void bspline8(float x, float* __restrict__ out) {
    float t[12];
    #pragma unroll
    for (int j = 0; j < 12; ++j) t[j] = (float)(j - 3) * 0.4f - 1.0f;

    float b[11];
    #pragma unroll
    for (int j = 0; j < 11; ++j)
        b[j] = (x >= t[j] && x < t[j + 1]) ? 1.0f : 0.0f;

    #pragma unroll
    for (int k = 1; k <= 3; ++k) {
        const float inv = 1.0f / (0.4f * (float)k);
        #pragma unroll
        for (int j = 0; j < 10; ++j) {
            if (j < 11 - k) {
                b[j] = (x - t[j]) * inv * b[j]
                     + (t[j + k + 1] - x) * inv * b[j + 1];
            }
        }
    }
    #pragma unroll
    for (int s = 0; s < NC; ++s) out[s] = b[s];
}

// ---- Kernel A: weight fusing + tiled feature precompute in one launch.
// blockIdx.y in [0, BB*CIN*NTILES): featgen for that (b, cin, tile).
// blockIdx.y == BB*CIN*NTILES    : grid-stride fuse of the weights.
__global__ void kan_prep_kernel(const float* __restrict__ x,
                                const float* __restrict__ base_w,
                                const float* __restrict__ spline_w,
                                const float* __restrict__ spline_s)
{
    if (blockIdx.y == BB * CIN * NTILES) {
        for (int i = blockIdx.x * blockDim.x + threadIdx.x;
             i < CIN * WCHUNK; i += gridDim.x * blockDim.x) {
            const int oc  = i & (COUT - 1);
            const int tap = (i / COUT) % K2;
            const int f   = (i / (COUT * K2)) % NF;
            const int c   = i / WCHUNK;
            const int widx = (oc * CIN + c) * K2 + tap;
            float w;
            if (f == 0) w = base_w[widx];
            else        w = spline_w[widx * NC + (f - 1)] * spline_s[widx];
            g_fused[i] = w;
        }
        return;
    }

    const int px = blockIdx.x * blockDim.x + threadIdx.x;
    if (px >= FPIX_R) return;
    const int bc   = blockIdx.y >> 4;       // b*CIN + c
    const int tile = blockIdx.y & 15;
    const int th0  = (tile >> 2) * TILE;
    const int tw0  = (tile & 3) * TILE;

    const int hr = px / FCR;
    const int hc = px % FCR;
    const int gh = th0 + hr - 1;
    const int gw = tw0 + hc - 1;
    float v = 0.0f;
    if (gh >= 0 && gh < HH && gw >= 0 && gw < WW)
        v = x[bc * (HH * WW) + gh * WW + gw];
    float bs[NC];
    bspline8(v, bs);

    float* dst = g_feat_t + ((size_t)blockIdx.y) * SF_FLOATS;
    const int o = hr * FCP + hc + SWZ(hr);
    dst[o] = silu_f(v);
    #pragma unroll
    for (int s = 0; s < NC; ++s)
        dst[(s + 1) * FPIX_S + o] = bs[s];
}

// ---- Kernel B: main conv.
// 256 CTAs x 512 threads: ocg = tid >> 6 (8 groups of 4 oc);
// pxg = tid & 63 -> 2x2 pixel block: pr = pxg>>3, pc = pxg&7.
// Per tap: 1 broadcast LDS.128 feeds 8 FFMA2 (4 px x 4 oc).
// Features + weights staged via cp.async memcpy of pre-swizzled tile images,
// double-buffered one cin ahead; ONE barrier per cin.
__global__ void __launch_bounds__(THREADS, 2)
kan_conv_kernel(float* __restrict__ out)
{
    __shared__ __align__(16) float sF[2][SF_FLOATS];
    __shared__ __align__(16) float sW[2][WCHUNK];

    const int tid  = threadIdx.x;
    const int tile = blockIdx.x;      // 0..15
    const int b    = blockIdx.y;      // 0..15
    const int th0  = (tile >> 2) * TILE;
    const int tw0  = (tile & 3) * TILE;

    const int ocg = tid >> 6;         // 0..7 (warp-uniform)
    const int pxg = tid & 63;
    const int pr  = pxg >> 3;         // 0..7 -> rows 2pr, 2pr+1
    const int pc  = pxg & 7;          // 0..7 -> cols 2pc, 2pc+1

    // cp.async staged copy of one cin's tile image + weight chunk.
    auto prefetch = [&](int c, int bufIdx) {
        const float4* fsrc = reinterpret_cast<const float4*>(
            g_feat_t + ((size_t)((b * CIN + c) * NTILES + tile)) * SF_FLOATS);
        const uint32_t fdst =
            (uint32_t)__cvta_generic_to_shared(&sF[bufIdx][0]);
        #pragma unroll
        for (int k = 0; k < 2; ++k) {
            const int i = tid + k * THREADS;
            if (i < SF_FLOATS / 4)              // 810
                cp_async16(fdst + i * 16, fsrc + i);
        }
        const float4* wsrc =
            reinterpret_cast<const float4*>(g_fused + c * WCHUNK);
        const uint32_t wdst =
            (uint32_t)__cvta_generic_to_shared(&sW[bufIdx][0]);
        #pragma unroll
        for (int k = 0; k < 2; ++k) {
            const int i = tid + k * THREADS;
            if (i < WCHUNK / 4)                 // 648
                cp_async16(wdst + i * 16, wsrc + i);
        }
        asm volatile("cp.async.commit_group;");
    };

    // Accumulators: 4 px x 4 oc = 16 floats as 8 packed f32x2.
    unsigned long long acc[4][2];
    #pragma unroll
    for (int p = 0; p < 4; ++p) { acc[p][0] = 0ULL; acc[p][1] = 0ULL; }

    prefetch(0, 0);

    for (int c = 0; c < CIN; ++c) {
        const int buf = c & 1;

        if (c < CIN - 1) {
            prefetch(c + 1, 1 - buf);
            asm volatile("cp.async.wait_group 1;");   // group(c) arrived
        } else {
            asm volatile("cp.async.wait_group 0;");
        }
        __syncthreads();   // buf(c) visible to all; conv(c-1) done with buf^1

        const float* __restrict__ sFb = sF[buf];
        const float* __restrict__ sWb = sW[buf];

        #pragma unroll 3
        for (int f = 0; f < NF; ++f) {
            const float* fpl = sFb + f * FPIX_S;

            // rolling window rows: rw[0] = row (2pr+dh), rw[1] = next row
            unsigned long long rw[2][4];
            #pragma unroll
            for (int k = 0; k < 2; ++k) {
                const int row = 2 * pr + k;
                const int base = row * FCP + 2 * pc + SWZ(row);
                #pragma unroll
                for (int wc = 0; wc < 4; ++wc)
                    rw[k][wc] = pack2(fpl[base + wc]);
            }

            const float* wbase = sWb + (f * K2) * COUT + ocg * 4;

            #pragma unroll
            for (int dh = 0; dh < 3; ++dh) {
                #pragma unroll
                for (int dw = 0; dw < 3; ++dw) {
                    const int tap = dh * 3 + dw;
                    const ulonglong2 w = *reinterpret_cast<const ulonglong2*>(
                        wbase + tap * COUT);
                    #pragma unroll
                    for (int i = 0; i < 2; ++i) {
                        #pragma unroll
                        for (int j = 0; j < 2; ++j) {
                            const unsigned long long fv = rw[i][j + dw];
                            ffma2(acc[i * 2 + j][0], fv, w.x);
                            ffma2(acc[i * 2 + j][1], fv, w.y);
                        }
                    }
                }
                // rotate window: bring in row (2pr + dh + 2)
                if (dh < 2) {
                    #pragma unroll
                    for (int wc = 0; wc < 4; ++wc) rw[0][wc] = rw[1][wc];
                    const int row = 2 * pr + dh + 2;
                    const int base = row * FCP + 2 * pc + SWZ(row);
                    #pragma unroll
                    for (int wc = 0; wc < 4; ++wc)
                        rw[1][wc] = pack2(fpl[base + wc]);
                }
            }
        }
        __syncthreads();   // conv(c) done reading buf before prefetch(c+2)
    }

    // ---- write out: 2 rows x 2 cols x 4 oc per thread, float2 over cols ----
    const int gh0 = th0 + 2 * pr;
    const int gw0 = tw0 + 2 * pc;
    #pragma unroll
    for (int i = 0; i < 2; ++i) {
        #pragma unroll
        for (int q = 0; q < 2; ++q) {
            const int oc = ocg * 4 + 2 * q;
            float l0, h0, l1, h1;
            unpack2(acc[i * 2 + 0][q], l0, h0);
            unpack2(acc[i * 2 + 1][q], l1, h1);
            float2* p0 = reinterpret_cast<float2*>(
                &out[((b * COUT + oc + 0) * HH + gh0 + i) * WW + gw0]);
            float2* p1 = reinterpret_cast<float2*>(
                &out[((b * COUT + oc + 1) * HH + gh0 + i) * WW + gw0]);
            *p0 = make_float2(l0, l1);
            *p1 = make_float2(h0, h1);
        }
    }
}

extern "C" void kernel_launch(void* const* d_in, const int* in_sizes, int n_in,
                              void* d_out, int out_size) {
    const float* x   = (const float*)d_in[0];
    const float* bw  = (const float*)d_in[1];
    const float* sw  = (const float*)d_in[2];
    const float* ss  = (const float*)d_in[3];
    float* out       = (float*)d_out;

    // One prep launch: tiled featgen (y < BB*CIN*NTILES) + weight fuse.
    dim3 pgrid((FPIX_R + 255) / 256, BB * CIN * NTILES + 1);
    kan_prep_kernel<<<pgrid, 256>>>(x, bw, sw, ss);

    dim3 grid(NTILES, BB);   // 16 tiles x 16 batches = 256 CTAs x 512 thr
    kan_conv_kernel<<<grid, THREADS>>>(out);
}

// round 14
// speedup vs baseline: 1.0822x; 1.0822x over previous
#include <cuda_runtime.h>
#include <cstdint>

// Problem constants
#define BB   16
#define CIN  8
#define COUT 32
#define HH   64
#define WW   64
#define K2   9
#define NC   8          // spline coefficients per feature
#define NF   9          // features per cin: silu + 8 spline bases
#define TILE 16
#define NTILES 16       // 4x4 tiles of 16x16
#define THREADS 512

#define FR    18                       // halo rows
#define FCR   18                       // real halo cols
#define FCP   20                       // padded col stride (+swizzle slot)
#define FPIX_S (FR * FCP)              // 360 floats per plane (stored)
#define FPIX_R (FR * FCR)              // 324 real pixels
#define SF_FLOATS (NF * FPIX_S)        // 3240
#define WCHUNK   (NF * K2 * COUT)      // 2592 floats per cin

// Flat featgen decomposition
#define NSLICES   (BB * CIN * NTILES)          // 2048
#define FEAT_WORK (NSLICES * FPIX_R)           // 663552
#define PREP_T    256
#define NB_FEAT   ((FEAT_WORK + PREP_T - 1) / PREP_T)   // 2592
#define NB_FUSE   ((CIN * WCHUNK + PREP_T - 1) / PREP_T) // 81

// Row swizzle: +1 for rows whose pair-index is odd -> warp feature LDS
// spreads across all 32 banks (2x2 px blocking makes raw offsets even).
#define SWZ(hr) (((hr) >> 1) & 1)

// Fused weights + tiled, swizzle-baked feature images (kan_prep_kernel).
// g_feat_t[(b*CIN+c)*NTILES + tile][f][FPIX_S] == exact smem image per tile.
__device__ float g_fused[CIN * WCHUNK];
__device__ float g_feat_t[(size_t)NSLICES * SF_FLOATS];   // ~26.5 MB

__device__ __forceinline__ float silu_f(float x) {
    return x / (1.0f + __expf(-x));
}

// Packed f32x2 FMA: one issue slot, two fp32 FMAs, bit-identical rounding.
__device__ __forceinline__ void ffma2(unsigned long long& d,
                                      unsigned long long a,
                                      unsigned long long b) {
    asm("fma.rn.f32x2 %0, %1, %2, %0;" : "+l"(d) : "l"(a), "l"(b));
}

__device__ __forceinline__ unsigned long long pack2(float v) {
    unsigned long long p;
    asm("mov.b64 %0, {%1, %1};" : "=l"(p) : "f"(v));
    return p;
}

__device__ __forceinline__ void unpack2(unsigned long long p, float& lo, float& hi) {
    asm("mov.b64 {%0, %1}, %2;" : "=f"(lo), "=f"(hi) : "l"(p));
}

__device__ __forceinline__ void cp_async16(uint32_t saddr, const void* gptr) {
    asm volatile("cp.async.cg.shared.global [%0], [%1], 16;"
                 :: "r"(saddr), "l"(gptr));
}

// De Boor-Cox recursion, degree 3, uniform knots t[j] = (j-3)*0.4 - 1.0.
// Uniform knots => denominators are exactly k*h; divisions replaced by
// compile-time reciprocal multiplies (deviation ~1e-7, tolerance 1e-3).
__device__ __forceinline__ void bspline8(float x, float* __restrict__ out) {
    float t[12];
    #pragma unroll
    for (int j = 0; j < 12; ++j) t[j] = (float)(j - 3) * 0.4f - 1.0f;

    float b[11];
    #pragma unroll
    for (int j = 0; j < 11; ++j)
        b[j] = (x >= t[j] && x < t[j + 1]) ? 1.0f : 0.0f;

    #pragma unroll
    for (int k = 1; k <= 3; ++k) {
        const float inv = 1.0f / (0.4f * (float)k);
        #pragma unroll
        for (int j = 0; j < 10; ++j) {
            if (j < 11 - k) {
                b[j] = (x - t[j]) * inv * b[j]
                     + (t[j + k + 1] - x) * inv * b[j + 1];
            }
        }
    }
    #pragma unroll
    for (int s = 0; s < NC; ++s) out[s] = b[s];
}

// ---- Kernel A: weight fusing + tiled feature precompute, one flat launch.
// Blocks [0, NB_FEAT): featgen, one thread per real tile-pixel (all full).
// Blocks [NB_FEAT, NB_FEAT+NB_FUSE): weight fuse.
__global__ void kan_prep_kernel(const float* __restrict__ x,
                                const float* __restrict__ base_w,
                                const float* __restrict__ spline_w,
                                const float* __restrict__ spline_s)
{
    if (blockIdx.x >= NB_FEAT) {
        const int i = (blockIdx.x - NB_FEAT) * PREP_T + threadIdx.x;
        if (i < CIN * WCHUNK) {
            const int oc  = i & (COUT - 1);
            const int tap = (i / COUT) % K2;
            const int f   = (i / (COUT * K2)) % NF;
            const int c   = i / WCHUNK;
            const int widx = (oc * CIN + c) * K2 + tap;
            float w;
            if (f == 0) w = base_w[widx];
            else        w = spline_w[widx * NC + (f - 1)] * spline_s[widx];
            g_fused[i] = w;
        }
        return;
    }

    const int idx = blockIdx.x * PREP_T + threadIdx.x;
    if (idx >= FEAT_WORK) return;
    const int slice = idx / FPIX_R;          // bc*NTILES + tile
    const int px    = idx - slice * FPIX_R;
    const int bc    = slice >> 4;            // b*CIN + c
    const int tile  = slice & 15;
    const int th0   = (tile >> 2) * TILE;
    const int tw0   = (tile & 3) * TILE;

    const int hr = px / FCR;
    const int hc = px % FCR;
    const int gh = th0 + hr - 1;
    const int gw = tw0 + hc - 1;
    float v = 0.0f;
    if (gh >= 0 && gh < HH && gw >= 0 && gw < WW)
        v = x[bc * (HH * WW) + gh * WW + gw];
    float bs[NC];
    bspline8(v, bs);

    float* dst = g_feat_t + (size_t)slice * SF_FLOATS;
    const int o = hr * FCP + hc + SWZ(hr);
    dst[o] = silu_f(v);
    #pragma unroll
    for (int s = 0; s < NC; ++s)
        dst[(s + 1) * FPIX_S + o] = bs[s];
}

// ---- Kernel B: main conv (unchanged from R13 — best conv so far).
// 256 CTAs x 512 threads: ocg = tid >> 6 (8 groups of 4 oc);
// pxg = tid & 63 -> 2x2 pixel block: pr = pxg>>3, pc = pxg&7.
// Per tap: 1 broadcast LDS.128 feeds 8 FFMA2 (4 px x 4 oc).
// Features + weights staged via cp.async memcpy of pre-swizzled tile images,
// double-buffered one cin ahead.
__global__ void __launch_bounds__(THREADS, 2)
kan_conv_kernel(float* __restrict__ out)
{
    __shared__ __align__(16) float sF[2][SF_FLOATS];
    __shared__ __align__(16) float sW[2][WCHUNK];

    const int tid  = threadIdx.x;
    const int tile = blockIdx.x;      // 0..15
    const int b    = blockIdx.y;      // 0..15
    const int th0  = (tile >> 2) * TILE;
    const int tw0  = (tile & 3) * TILE;

    const int ocg = tid >> 6;         // 0..7 (warp-uniform)
    const int pxg = tid & 63;
    const int pr  = pxg >> 3;         // 0..7 -> rows 2pr, 2pr+1
    const int pc  = pxg & 7;          // 0..7 -> cols 2pc, 2pc+1

    // cp.async staged copy of one cin's tile image + weight chunk.
    auto prefetch = [&](int c, int bufIdx) {
        const float4* fsrc = reinterpret_cast<const float4*>(
            g_feat_t + ((size_t)((b * CIN + c) * NTILES + tile)) * SF_FLOATS);
        const uint32_t fdst =
            (uint32_t)__cvta_generic_to_shared(&sF[bufIdx][0]);
        #pragma unroll
        for (int k = 0; k < 2; ++k) {
            const int i = tid + k * THREADS;
            if (i < SF_FLOATS / 4)              // 810
                cp_async16(fdst + i * 16, fsrc + i);
        }
        const float4* wsrc =
            reinterpret_cast<const float4*>(g_fused + c * WCHUNK);
        const uint32_t wdst =
            (uint32_t)__cvta_generic_to_shared(&sW[bufIdx][0]);
        #pragma unroll
        for (int k = 0; k < 2; ++k) {
            const int i = tid + k * THREADS;
            if (i < WCHUNK / 4)                 // 648
                cp_async16(wdst + i * 16, wsrc + i);
        }
        asm volatile("cp.async.commit_group;");
    };

    // Accumulators: 4 px x 4 oc = 16 floats as 8 packed f32x2.
    unsigned long long acc[4][2];
    #pragma unroll
    for (int p = 0; p < 4; ++p) { acc[p][0] = 0ULL; acc[p][1] = 0ULL; }

    prefetch(0, 0);

    for (int c = 0; c < CIN; ++c) {
        const int buf = c & 1;

        if (c < CIN - 1) {
            prefetch(c + 1, 1 - buf);
            asm volatile("cp.async.wait_group 1;");   // group(c) arrived
        } else {
            asm volatile("cp.async.wait_group 0;");
        }
        __syncthreads();   // buf(c) visible to all; conv(c-1) done with buf^1

        const float* __restrict__ sFb = sF[buf];
        const float* __restrict__ sWb = sW[buf];

        #pragma unroll 3
        for (int f = 0; f < NF; ++f) {
            const float* fpl = sFb + f * FPIX_S;

            // rolling window rows: rw[0] = row (2pr+dh), rw[1] = next row
            unsigned long long rw[2][4];
            #pragma unroll
            for (int k = 0; k < 2; ++k) {
                const int row = 2 * pr + k;
                const int base = row * FCP + 2 * pc + SWZ(row);
                #pragma unroll
                for (int wc = 0; wc < 4; ++wc)
                    rw[k][wc] = pack2(fpl[base + wc]);
            }

            const float* wbase = sWb + (f * K2) * COUT + ocg * 4;

            #pragma unroll
            for (int dh = 0; dh < 3; ++dh) {
                #pragma unroll
                for (int dw = 0; dw < 3; ++dw) {
                    const int tap = dh * 3 + dw;
                    const ulonglong2 w = *reinterpret_cast<const ulonglong2*>(
                        wbase + tap * COUT);
                    #pragma unroll
                    for (int i = 0; i < 2; ++i) {
                        #pragma unroll
                        for (int j = 0; j < 2; ++j) {
                            const unsigned long long fv = rw[i][j + dw];
                            ffma2(acc[i * 2 + j][0], fv, w.x);
                            ffma2(acc[i * 2 + j][1], fv, w.y);
                        }
                    }
                }
                // rotate window: bring in row (2pr + dh + 2)
                if (dh < 2) {
                    #pragma unroll
                    for (int wc = 0; wc < 4; ++wc) rw[0][wc] = rw[1][wc];
                    const int row = 2 * pr + dh + 2;
                    const int base = row * FCP + 2 * pc + SWZ(row);
                    #pragma unroll
                    for (int wc = 0; wc < 4; ++wc)
                        rw[1][wc] = pack2(fpl[base + wc]);
                }
            }
        }
        __syncthreads();   // conv(c) done reading buf before prefetch(c+2)
    }

    // ---- write out: 2 rows x 2 cols x 4 oc per thread, float2 over cols ----
    const int gh0 = th0 + 2 * pr;
    const int gw0 = tw0 + 2 * pc;
    #pragma unroll
    for (int i = 0; i < 2; ++i) {
        #pragma unroll
        for (int q = 0; q < 2; ++q) {
            const int oc = ocg * 4 + 2 * q;
            float l0, h0, l1, h1;
            unpack2(acc[i * 2 + 0][q], l0, h0);
            unpack2(acc[i * 2 + 1][q], l1, h1);
            float2* p0 = reinterpret_cast<float2*>(
                &out[((b * COUT + oc + 0) * HH + gh0 + i) * WW + gw0]);
            float2* p1 = reinterpret_cast<float2*>(
                &out[((b * COUT + oc + 1) * HH + gh0 + i) * WW + gw0]);
            *p0 = make_float2(l0, l1);
            *p1 = make_float2(h0, h1);
        }
    }
}

extern "C" void kernel_launch(void* const* d_in, const int* in_sizes, int n_in,
                              void* d_out, int out_size) {
    const float* x   = (const float*)d_in[0];
    const float* bw  = (const float*)d_in[1];
    const float* sw  = (const float*)d_in[2];
    const float* ss  = (const float*)d_in[3];
    float* out       = (float*)d_out;

    // One flat prep launch: featgen blocks + fuse blocks.
    kan_prep_kernel<<<NB_FEAT + NB_FUSE, PREP_T>>>(x, bw, sw, ss);

    dim3 grid(NTILES, BB);   // 16 tiles x 16 batches = 256 CTAs x 512 thr
    kan_conv_kernel<<<grid, THREADS>>>(out);
}

// round 15
// speedup vs baseline: 1.1977x; 1.1067x over previous
#include <cuda_runtime.h>
#include <cstdint>

// Problem constants
#define BB   16
#define CIN  8
#define COUT 32
#define HH   64
#define WW   64
#define K2   9
#define NC   8          // spline coefficients per feature
#define NF   9          // features per cin: silu + 8 spline bases
#define TILE 8
#define NTILES 64       // 8x8 grid of 8x8 tiles
#define THREADS 128

#define FR    10                       // halo rows
#define FCR   10                       // real halo cols
#define FCP   12                       // padded col stride (conflict-free)
#define FPIX_S (FR * FCP)              // 120 floats per plane (stored)
#define FPIX_R (FR * FCR)              // 100 real pixels
#define SF_FLOATS (NF * FPIX_S)        // 1080
#define WCHUNK   (NF * K2 * COUT)      // 2592 floats per cin

// Flat featgen decomposition
#define NSLICES   (BB * CIN * NTILES)          // 8192
#define FEAT_WORK (NSLICES * FPIX_R)           // 819200
#define PREP_T    256
#define NB_FEAT   (FEAT_WORK / PREP_T)         // 3200 (exact)
#define NB_FUSE   ((CIN * WCHUNK + PREP_T - 1) / PREP_T)  // 81

// Fused weights + tiled feature images (exact smem layout, no swizzle:
// FCP=12 places the 4 even rows of a 2x2-blocked warp in disjoint bank
// octets {0,24,16,8} -> conflict-free feature LDS).
__device__ float g_fused[CIN * WCHUNK];
__device__ float g_feat_t[(size_t)NSLICES * SF_FLOATS];   // ~35.4 MB

__device__ __forceinline__ float silu_f(float x) {
    return x / (1.0f + __expf(-x));
}

// Packed f32x2 FMA: one issue slot, two fp32 FMAs, bit-identical rounding.
__device__ __forceinline__ void ffma2(unsigned long long& d,
                                      unsigned long long a,
                                      unsigned long long b) {
    asm("fma.rn.f32x2 %0, %1, %2, %0;" : "+l"(d) : "l"(a), "l"(b));
}

__device__ __forceinline__ unsigned long long pack2(float v) {
    unsigned long long p;
    asm("mov.b64 %0, {%1, %1};" : "=l"(p) : "f"(v));
    return p;
}

__device__ __forceinline__ void unpack2(unsigned long long p, float& lo, float& hi) {
    asm("mov.b64 {%0, %1}, %2;" : "=f"(lo), "=f"(hi) : "l"(p));
}

__device__ __forceinline__ void cp_async16(uint32_t saddr, const void* gptr) {
    asm volatile("cp.async.cg.shared.global [%0], [%1], 16;"
                 :: "r"(saddr), "l"(gptr));
}

// De Boor-Cox recursion, degree 3, uniform knots t[j] = (j-3)*0.4 - 1.0.
// Uniform knots => denominators are exactly k*h; divisions replaced by
// compile-time reciprocal multiplies (deviation ~1e-7, tolerance 1e-3).
__device__ __forceinline__ void bspline8(float x, float* __restrict__ out) {
    float t[12];
    #pragma unroll
    for (int j = 0; j < 12; ++j) t[j] = (float)(j - 3) * 0.4f - 1.0f;

    float b[11];
    #pragma unroll
    for (int j = 0; j < 11; ++j)
        b[j] = (x >= t[j] && x < t[j + 1]) ? 1.0f : 0.0f;

    #pragma unroll
    for (int k = 1; k <= 3; ++k) {
        const float inv = 1.0f / (0.4f * (float)k);
        #pragma unroll
        for (int j = 0; j < 10; ++j) {
            if (j < 11 - k) {
                b[j] = (x - t[j]) * inv * b[j]
                     + (t[j + k + 1] - x) * inv * b[j + 1];
            }
        }
    }
    #pragma unroll
    for (int s = 0; s < NC; ++s) out[s] = b[s];
}

// ---- Kernel A: weight fusing + tiled feature precompute, one flat launch.
__global__ void kan_prep_kernel(const float* __restrict__ x,
                                const float* __restrict__ base_w,
                                const float* __restrict__ spline_w,
                                const float* __restrict__ spline_s)
{
    if (blockIdx.x >= NB_FEAT) {
        const int i = (blockIdx.x - NB_FEAT) * PREP_T + threadIdx.x;
        if (i < CIN * WCHUNK) {
            const int oc  = i & (COUT - 1);
            const int tap = (i / COUT) % K2;
            const int f   = (i / (COUT * K2)) % NF;
            const int c   = i / WCHUNK;
            const int widx = (oc * CIN + c) * K2 + tap;
            float w;
            if (f == 0) w = base_w[widx];
            else        w = spline_w[widx * NC + (f - 1)] * spline_s[widx];
            g_fused[i] = w;
        }
        return;
    }

    const int idx = blockIdx.x * PREP_T + threadIdx.x;
    const int slice = idx / FPIX_R;          // (b*CIN+c)*NTILES + tile
    const int px    = idx - slice * FPIX_R;
    const int bc    = slice >> 6;            // b*CIN + c
    const int tile  = slice & 63;
    const int th0   = (tile >> 3) * TILE;
    const int tw0   = (tile & 7) * TILE;

    const int hr = px / FCR;
    const int hc = px % FCR;
    const int gh = th0 + hr - 1;
    const int gw = tw0 + hc - 1;
    float v = 0.0f;
    if (gh >= 0 && gh < HH && gw >= 0 && gw < WW)
        v = x[bc * (HH * WW) + gh * WW + gw];
    float bs[NC];
    bspline8(v, bs);

    float* dst = g_feat_t + (size_t)slice * SF_FLOATS;
    const int o = hr * FCP + hc;
    dst[o] = silu_f(v);
    #pragma unroll
    for (int s = 0; s < NC; ++s)
        dst[(s + 1) * FPIX_S + o] = bs[s];
}

// ---- Kernel B: main conv.
// 1024 CTAs x 128 threads -> 7 CTAs/SM, ONE balanced wave (imbalance ~1%).
// Thread: ocg = tid >> 4 (8 groups of 4 oc); pxb = tid & 15 -> 2x2 pixel
// block: pr = pxb>>2 (rows 2pr,2pr+1), pc = pxb&3 (cols 2pc,2pc+1).
// Per tap: 1 LDS.128 (broadcast per half-warp) feeds 8 FFMA2 (4 px x 4 oc).
// Features + weights staged via cp.async of pre-baked tile images,
// double-buffered one cin ahead.
__global__ void __launch_bounds__(THREADS, 8)
kan_conv_kernel(float* __restrict__ out)
{
    __shared__ __align__(16) float sF[2][SF_FLOATS];
    __shared__ __align__(16) float sW[2][WCHUNK];

    const int tid  = threadIdx.x;
    const int tile = blockIdx.x;      // 0..63
    const int b    = blockIdx.y;      // 0..15
    const int th0  = (tile >> 3) * TILE;
    const int tw0  = (tile & 7) * TILE;

    const int ocg = tid >> 4;         // 0..7
    const int pxb = tid & 15;
    const int pr  = pxb >> 2;         // 0..3 -> rows 2pr, 2pr+1
    const int pc  = pxb & 3;          // 0..3 -> cols 2pc, 2pc+1

    // cp.async staged copy of one cin's tile image + weight chunk.
    auto prefetch = [&](int c, int bufIdx) {
        const float4* fsrc = reinterpret_cast<const float4*>(
            g_feat_t + ((size_t)((b * CIN + c) * NTILES + tile)) * SF_FLOATS);
        const uint32_t fdst =
            (uint32_t)__cvta_generic_to_shared(&sF[bufIdx][0]);
        #pragma unroll
        for (int k = 0; k < 3; ++k) {
            const int i = tid + k * THREADS;
            if (i < SF_FLOATS / 4)              // 270
                cp_async16(fdst + i * 16, fsrc + i);
        }
        const float4* wsrc =
            reinterpret_cast<const float4*>(g_fused + c * WCHUNK);
        const uint32_t wdst =
            (uint32_t)__cvta_generic_to_shared(&sW[bufIdx][0]);
        #pragma unroll
        for (int k = 0; k < 6; ++k) {
            const int i = tid + k * THREADS;
            if (i < WCHUNK / 4)                 // 648
                cp_async16(wdst + i * 16, wsrc + i);
        }
        asm volatile("cp.async.commit_group;");
    };

    // Accumulators: 4 px x 4 oc = 16 floats as 8 packed f32x2.
    unsigned long long acc[4][2];
    #pragma unroll
    for (int p = 0; p < 4; ++p) { acc[p][0] = 0ULL; acc[p][1] = 0ULL; }

    prefetch(0, 0);

    for (int c = 0; c < CIN; ++c) {
        const int buf = c & 1;

        if (c < CIN - 1) {
            prefetch(c + 1, 1 - buf);
            asm volatile("cp.async.wait_group 1;");   // group(c) arrived
        } else {
            asm volatile("cp.async.wait_group 0;");
        }
        __syncthreads();   // buf(c) visible; conv(c-1) done with buf^1

        const float* __restrict__ sFb = sF[buf];
        const float* __restrict__ sWb = sW[buf];

        #pragma unroll 3
        for (int f = 0; f < NF; ++f) {
            const float* fpl = sFb + f * FPIX_S;

            // rolling window rows: rw[0] = row (2pr+dh), rw[1] = next row
            unsigned long long rw[2][4];
            #pragma unroll
            for (int k = 0; k < 2; ++k) {
                const int base = (2 * pr + k) * FCP + 2 * pc;
                #pragma unroll
                for (int wc = 0; wc < 4; ++wc)
                    rw[k][wc] = pack2(fpl[base + wc]);
            }

            const float* wbase = sWb + (f * K2) * COUT + ocg * 4;

            #pragma unroll
            for (int dh = 0; dh < 3; ++dh) {
                #pragma unroll
                for (int dw = 0; dw < 3; ++dw) {
                    const int tap = dh * 3 + dw;
                    const ulonglong2 w = *reinterpret_cast<const ulonglong2*>(
                        wbase + tap * COUT);
                    #pragma unroll
                    for (int i = 0; i < 2; ++i) {
                        #pragma unroll
                        for (int j = 0; j < 2; ++j) {
                            const unsigned long long fv = rw[i][j + dw];
                            ffma2(acc[i * 2 + j][0], fv, w.x);
                            ffma2(acc[i * 2 + j][1], fv, w.y);
                        }
                    }
                }
                // rotate window: bring in row (2pr + dh + 2)
                if (dh < 2) {
                    #pragma unroll
                    for (int wc = 0; wc < 4; ++wc) rw[0][wc] = rw[1][wc];
                    const int base = (2 * pr + dh + 2) * FCP + 2 * pc;
                    #pragma unroll
                    for (int wc = 0; wc < 4; ++wc)
                        rw[1][wc] = pack2(fpl[base + wc]);
                }
            }
        }
        __syncthreads();   // conv(c) done reading buf before prefetch(c+2)
    }

    // ---- write out: 2 rows x 2 cols x 4 oc per thread, float2 over cols ----
    const int gh0 = th0 + 2 * pr;
    const int gw0 = tw0 + 2 * pc;
    #pragma unroll
    for (int i = 0; i < 2; ++i) {
        #pragma unroll
        for (int q = 0; q < 2; ++q) {
            const int oc = ocg * 4 + 2 * q;
            float l0, h0, l1, h1;
            unpack2(acc[i * 2 + 0][q], l0, h0);
            unpack2(acc[i * 2 + 1][q], l1, h1);
            float2* p0 = reinterpret_cast<float2*>(
                &out[((b * COUT + oc + 0) * HH + gh0 + i) * WW + gw0]);
            float2* p1 = reinterpret_cast<float2*>(
                &out[((b * COUT + oc + 1) * HH + gh0 + i) * WW + gw0]);
            *p0 = make_float2(l0, l1);
            *p1 = make_float2(h0, h1);
        }
    }
}

extern "C" void kernel_launch(void* const* d_in, const int* in_sizes, int n_in,
                              void* d_out, int out_size) {
    const float* x   = (const float*)d_in[0];
    const float* bw  = (const float*)d_in[1];
    const float* sw  = (const float*)d_in[2];
    const float* ss  = (const float*)d_in[3];
    float* out       = (float*)d_out;

    // One flat prep launch: featgen blocks + fuse blocks.
    kan_prep_kernel<<<NB_FEAT + NB_FUSE, PREP_T>>>(x, bw, sw, ss);

    // Maximize smem carveout so 7 CTAs/SM (29.4 KB each) are resident.
    cudaFuncSetAttribute(kan_conv_kernel,
                         cudaFuncAttributePreferredSharedMemoryCarveout, 100);

    dim3 grid(NTILES, BB);   // 64 tiles x 16 batches = 1024 CTAs x 128 thr
    kan_conv_kernel<<<grid, THREADS>>>(out);
}